// round 1
// baseline (speedup 1.0000x reference)
#include <cuda_runtime.h>

#define THREADS        256
#define WARPS          8
#define ROWS_PER_WARP  8
#define ROWS_PER_BLOCK 64          // WARPS * ROWS_PER_WARP
#define DIN            4096
#define DOUT           4096
#define RNK            16
#define KT             512         // A k-tile staged in smem
#define APAD           20          // floats per A-row in smem (conflict-free pitch)
#define NBLOCKS        128         // 8192 rows / 64

__device__ __forceinline__ unsigned long long pk2(float v) {
    unsigned long long r;
    asm("mov.b64 %0, {%1, %1};" : "=l"(r) : "f"(v));
    return r;
}
__device__ __forceinline__ void ffma2(unsigned long long &acc,
                                      unsigned long long a, unsigned long long b) {
    // acc = a * b + acc  (packed 2x fp32)
    asm("fma.rn.f32x2 %0, %1, %2, %0;" : "+l"(acc) : "l"(a), "l"(b));
}
__device__ __forceinline__ unsigned long long add2(unsigned long long a,
                                                   unsigned long long b) {
    unsigned long long d;
    asm("add.rn.f32x2 %0, %1, %2;" : "=l"(d) : "l"(a), "l"(b));
    return d;
}

__global__ void __launch_bounds__(THREADS, 1)
lora_fused_kernel(const float* __restrict__ x,
                  const float* __restrict__ A,
                  const float* __restrict__ B,
                  float* __restrict__ out)
{
    __shared__ float As[KT * APAD];               // 40 KB, pitch 20 floats
    __shared__ float ts[ROWS_PER_BLOCK][RNK];     // 4 KB, t = x@A for this block

    const int tid  = threadIdx.x;
    const int lane = tid & 31;
    const int warp = tid >> 5;
    const long long rowBase  = (long long)blockIdx.x * ROWS_PER_BLOCK;
    const int       warpRow0 = warp * ROWS_PER_WARP;

    // ---------------- Phase 1: t[64,16] = x_rows @ A ----------------
    unsigned long long acc[ROWS_PER_WARP][8];     // 8 rows x 16 fp32 (as 8x f32x2)
    #pragma unroll
    for (int r = 0; r < ROWS_PER_WARP; r++)
        #pragma unroll
        for (int i = 0; i < 8; i++) acc[r][i] = 0ULL;

    const float* xw = x + (rowBase + warpRow0) * (long long)DIN;

    for (int t0 = 0; t0 < DIN; t0 += KT) {
        __syncthreads();
        // cooperative load of A[t0 : t0+KT][0:16] into padded smem
        {
            const float4* Ag = reinterpret_cast<const float4*>(A + (long long)t0 * RNK);
            #pragma unroll
            for (int m = 0; m < (KT * RNK / 4) / THREADS; m++) {
                int f = tid + m * THREADS;        // float4 index: k = f/4, q = f%4
                int k = f >> 2, q = f & 3;
                float4 v = Ag[f];
                *reinterpret_cast<float4*>(&As[k * APAD + q * 4]) = v;
            }
        }
        __syncthreads();

        #pragma unroll 4
        for (int jj = 0; jj < KT / 32; jj++) {
            const int k = lane + jj * 32;
            // batch 8 x-loads (one per row) for MLP
            float xv[ROWS_PER_WARP];
            #pragma unroll
            for (int r = 0; r < ROWS_PER_WARP; r++)
                xv[r] = xw[(long long)r * DIN + t0 + k];

            // A row for this k: 4x LDS.128, conflict-free via APAD=20
            const ulonglong2* ar = reinterpret_cast<const ulonglong2*>(&As[k * APAD]);
            ulonglong2 a0 = ar[0], a1 = ar[1], a2 = ar[2], a3 = ar[3];

            #pragma unroll
            for (int r = 0; r < ROWS_PER_WARP; r++) {
                unsigned long long x2 = pk2(xv[r]);
                ffma2(acc[r][0], x2, a0.x); ffma2(acc[r][1], x2, a0.y);
                ffma2(acc[r][2], x2, a1.x); ffma2(acc[r][3], x2, a1.y);
                ffma2(acc[r][4], x2, a2.x); ffma2(acc[r][5], x2, a2.y);
                ffma2(acc[r][6], x2, a3.x); ffma2(acc[r][7], x2, a3.y);
            }
        }
    }

    // butterfly reduce across the 32 lanes (each lane holds a partial dot)
    #pragma unroll
    for (int off = 16; off; off >>= 1)
        #pragma unroll
        for (int r = 0; r < ROWS_PER_WARP; r++)
            #pragma unroll
            for (int i = 0; i < 8; i++)
                acc[r][i] = add2(acc[r][i],
                                 __shfl_xor_sync(0xffffffffu, acc[r][i], off));

    if (lane == 0) {
        #pragma unroll
        for (int r = 0; r < ROWS_PER_WARP; r++) {
            unsigned long long* dst =
                reinterpret_cast<unsigned long long*>(ts[warpRow0 + r]);
            #pragma unroll
            for (int i = 0; i < 8; i++) dst[i] = acc[r][i];
        }
    }
    __syncthreads();

    // ---------------- Phase 2: out[64,4096] = t @ B ----------------
    // 4 column passes of 1024; each thread owns 4 output columns with
    // B[0:16][j:j+4] cached in registers and reused across all 64 rows.
    #pragma unroll 1
    for (int p = 0; p < 4; p++) {
        const int j = p * 1024 + tid * 4;
        ulonglong2 Breg[RNK];
        #pragma unroll
        for (int r = 0; r < RNK; r++)
            Breg[r] = *reinterpret_cast<const ulonglong2*>(B + (long long)r * DOUT + j);

        #pragma unroll 2
        for (int row = 0; row < ROWS_PER_BLOCK; row++) {
            // broadcast LDS of the 16 t-values for this row (all lanes same addr)
            const float4* tr = reinterpret_cast<const float4*>(ts[row]);
            float tv[RNK];
            *reinterpret_cast<float4*>(&tv[0])  = tr[0];
            *reinterpret_cast<float4*>(&tv[4])  = tr[1];
            *reinterpret_cast<float4*>(&tv[8])  = tr[2];
            *reinterpret_cast<float4*>(&tv[12]) = tr[3];

            unsigned long long accLo = 0ULL, accHi = 0ULL;
            #pragma unroll
            for (int r = 0; r < RNK; r++) {
                unsigned long long tp = pk2(tv[r]);
                ffma2(accLo, tp, Breg[r].x);
                ffma2(accHi, tp, Breg[r].y);
            }
            ulonglong2 o; o.x = accLo; o.y = accHi;
            *reinterpret_cast<ulonglong2*>(
                out + (rowBase + row) * (long long)DOUT + j) = o;
        }
    }
}

extern "C" void kernel_launch(void* const* d_in, const int* in_sizes, int n_in,
                              void* d_out, int out_size) {
    const float* x = (const float*)d_in[0];   // [4, 2048, 4096]
    const float* A = (const float*)d_in[1];   // [4096, 16]
    const float* B = (const float*)d_in[2];   // [16, 4096]
    float* out = (float*)d_out;               // [4, 2048, 4096]
    lora_fused_kernel<<<NBLOCKS, THREADS>>>(x, A, B, out);
}